// round 17
// baseline (speedup 1.0000x reference)
#include <cuda_runtime.h>
#include <cuda_bf16.h>
#include <math.h>
#include <cstdint>

#define L_ 512
#define B_ 64
#define E_ 256
#define H_ 256
#define T_ 12
#define CS 8    // cluster size (verified working)

typedef unsigned long long u64;

// ---------------- helpers ----------------
__device__ __forceinline__ float tanhap(float x) {
    float y;
    asm("tanh.approx.f32 %0, %1;" : "=f"(y) : "f"(x));
    return y;
}
__device__ __forceinline__ float sigap(float x) {
    return fmaf(0.5f, tanhap(0.5f * x), 0.5f);
}
__device__ __forceinline__ float ex2f(float x) {
    float y;
    asm("ex2.approx.f32 %0, %1;" : "=f"(y) : "f"(x));
    return y;
}
__device__ __forceinline__ float lg2f(float x) {
    float y;
    asm("lg2.approx.f32 %0, %1;" : "=f"(y) : "f"(x));
    return y;
}
__device__ __forceinline__ uint32_t smem_u32(const void* p) {
    uint32_t a;
    asm("{ .reg .u64 t; cvta.to.shared.u64 t, %1; cvt.u32.u64 %0, t; }" : "=r"(a) : "l"(p));
    return a;
}
__device__ __forceinline__ uint32_t packbf(float lo, float hi) {
    uint32_t r;
    asm("cvt.rn.bf16x2.f32 %0, %1, %2;" : "=r"(r) : "f"(hi), "f"(lo));
    return r;
}
__device__ __forceinline__ void ldsm_x4(uint32_t& r0, uint32_t& r1, uint32_t& r2, uint32_t& r3, uint32_t addr) {
    asm volatile("ldmatrix.sync.aligned.m8n8.x4.shared.b16 {%0,%1,%2,%3}, [%4];"
        : "=r"(r0), "=r"(r1), "=r"(r2), "=r"(r3) : "r"(addr));
}
__device__ __forceinline__ void mma16816(float& d0, float& d1, float& d2, float& d3,
                                         uint32_t a0, uint32_t a1, uint32_t a2, uint32_t a3,
                                         uint32_t b0, uint32_t b1) {
    asm volatile("mma.sync.aligned.m16n8k16.row.col.f32.bf16.bf16.f32 "
        "{%0,%1,%2,%3}, {%4,%5,%6,%7}, {%8,%9}, {%0,%1,%2,%3};"
        : "+f"(d0), "+f"(d1), "+f"(d2), "+f"(d3)
        : "r"(a0), "r"(a1), "r"(a2), "r"(a3), "r"(b0), "r"(b1));
}
__device__ __forceinline__ uint32_t mapa_rank(uint32_t local, uint32_t rank) {
    uint32_t r;
    asm("mapa.shared::cluster.u32 %0, %1, %2;" : "=r"(r) : "r"(local), "r"(rank));
    return r;
}
__device__ __forceinline__ void mbar_arrive_remote(uint32_t remAddr) {
    asm volatile("mbarrier.arrive.release.cluster.shared::cluster.b64 _, [%0];"
                 :: "r"(remAddr) : "memory");
}
__device__ __forceinline__ void mbar_wait_cluster(uint32_t mbar, uint32_t parity) {
    uint32_t done = 0;
    while (!done) {
        asm volatile(
            "{\n\t.reg .pred p;\n\t"
            "mbarrier.try_wait.parity.acquire.cluster.shared::cta.b64 p, [%1], %2, 0x989680;\n\t"
            "selp.b32 %0, 1, 0, p;\n\t}"
            : "=r"(done) : "r"(mbar), "r"(parity) : "memory");
    }
}

// ---------------- scratch ----------------
__device__ float g_gx[(size_t)2*L_*1024*B_];          // input gates TRANSPOSED: [2][L][gate-row j][b]
__device__ __nv_bfloat16 g_hb[(size_t)2*L_*B_*H_];    // hidden bf16
__device__ float g_emit[(size_t)L_*B_*T_];
__device__ float g_nll[B_];
__device__ int   g_done;                               // crf completion counter (self-resetting)

// ---------------- input-gate GEMM on HMMA (16 timesteps per CTA; R16-identical) ----------------
static const int IG_PITCH = 528;
static const int IG_SM_W  = 0;
static const int IG_SM_X  = 256 * IG_PITCH;
static const int IG_SM_TOK = IG_SM_X + 64 * IG_PITCH;
static const int INGATE_SMEM = IG_SM_TOK + 256;

__global__ __launch_bounds__(256, 1) void k_ingate(
    const int* __restrict__ sent, const float* __restrict__ emb,
    const float* __restrict__ Wf, const float* __restrict__ bfv,
    const float* __restrict__ Wb, const float* __restrict__ bbv)
{
    extern __shared__ __align__(1024) char smw[];
    uint32_t smb = smem_u32(smw);
    int* tok = (int*)(smw + IG_SM_TOK);
    int lg = blockIdx.x, jb = blockIdx.y;
    int dir = jb >> 2;
    int jjb = (jb & 3) * 256;
    int tid = threadIdx.x;
    int w = tid >> 5, l = tid & 31;
    const float* W  = dir ? Wb : Wf;
    const float* bv = dir ? bbv : bfv;

    {
        const float4* Wf4 = (const float4*)(W + (size_t)jjb*256);
        #pragma unroll 4
        for (int i = 0; i < 64; i++) {
            int idx = i*256 + tid;
            int r = idx >> 6, c4 = idx & 63;
            float4 v = Wf4[(size_t)r*64 + c4];
            *(uint2*)(smw + IG_SM_W + r*IG_PITCH + c4*8) =
                make_uint2(packbf(v.x, v.y), packbf(v.z, v.w));
        }
    }
    int mb = 32*w;
    int rr0 = mb + (l >> 2);
    float bias[4];
    #pragma unroll
    for (int i = 0; i < 4; i++) bias[i] = bv[jjb + rr0 + 8*i];

    uint32_t aAddr[2];
    #pragma unroll
    for (int mt = 0; mt < 2; mt++)
        aAddr[mt] = smb + IG_SM_W + (uint32_t)((mb + mt*16 + (l & 15))*IG_PITCH + (l >> 4)*16);
    uint32_t xAddr[8];
    {
        int lrow = l & 7, grp = l >> 3;
        #pragma unroll
        for (int nt = 0; nt < 8; nt++)
            xAddr[nt] = smb + IG_SM_X + (uint32_t)((nt*8 + lrow)*IG_PITCH + grp*16);
    }
    int cc2 = (l & 3)*2;

    for (int il = 0; il < 16; il++) {
        int lcur = lg*16 + il;
        __syncthreads();
        if (tid < 64) tok[tid] = sent[tid*L_ + lcur];
        __syncthreads();
        #pragma unroll 4
        for (int i = 0; i < 16; i++) {
            int idx = i*256 + tid;
            int r = idx >> 6, c4 = idx & 63;
            float4 v = ((const float4*)emb)[(size_t)tok[r]*64 + c4];
            *(uint2*)(smw + IG_SM_X + r*IG_PITCH + c4*8) =
                make_uint2(packbf(v.x, v.y), packbf(v.z, v.w));
        }
        __syncthreads();

        float acc[2][8][4];
        #pragma unroll
        for (int mt = 0; mt < 2; mt++)
            #pragma unroll
            for (int nt = 0; nt < 8; nt++)
                #pragma unroll
                for (int k = 0; k < 4; k++) acc[mt][nt][k] = 0.f;

        #pragma unroll 2
        for (int ktp = 0; ktp < 8; ktp++) {
            uint32_t af[2][2][4];
            #pragma unroll
            for (int mt = 0; mt < 2; mt++)
                #pragma unroll
                for (int kk = 0; kk < 2; kk++)
                    ldsm_x4(af[mt][kk][0], af[mt][kk][1], af[mt][kk][2], af[mt][kk][3],
                            aAddr[mt] + (ktp*2 + kk)*32);
            #pragma unroll
            for (int nt = 0; nt < 8; nt++) {
                uint32_t b0, b1, b2, b3;
                ldsm_x4(b0, b1, b2, b3, xAddr[nt] + ktp*64);
                #pragma unroll
                for (int mt = 0; mt < 2; mt++) {
                    mma16816(acc[mt][nt][0], acc[mt][nt][1], acc[mt][nt][2], acc[mt][nt][3],
                             af[mt][0][0], af[mt][0][1], af[mt][0][2], af[mt][0][3], b0, b1);
                    mma16816(acc[mt][nt][0], acc[mt][nt][1], acc[mt][nt][2], acc[mt][nt][3],
                             af[mt][1][0], af[mt][1][1], af[mt][1][2], af[mt][1][3], b2, b3);
                }
            }
        }

        float* outb = g_gx + ((size_t)(dir*L_ + lcur)*1024 + jjb)*64;
        #pragma unroll
        for (int mt = 0; mt < 2; mt++) {
            int ra = mb + mt*16 + (l >> 2);
            int rb = ra + 8;
            float ba = bias[mt*2 + 0];
            float bb2 = bias[mt*2 + 1];
            #pragma unroll
            for (int nt = 0; nt < 8; nt++) {
                *(float2*)(outb + (size_t)ra*64 + nt*8 + cc2) =
                    make_float2(acc[mt][nt][0] + ba, acc[mt][nt][1] + ba);
                *(float2*)(outb + (size_t)rb*64 + nt*8 + cc2) =
                    make_float2(acc[mt][nt][2] + bb2, acc[mt][nt][3] + bb2);
            }
        }
    }
}

// ---------------- persistent LSTM: warp-local epilogue (no Ps, 2 barriers/step) ----------------
// 128 CTAs = (dir 2) x (batch-eighth 8) x (rank 8). CTA owns hids [32p,32p+32), batches [8be,8be+8).
// Warp w owns hids hb+4w..+4, ALL 4 gates (A rows: r = gate_pair layout).
// Lane l: hid_l=(l>>2)&3, g0=l>>4; holds gates g0, g0+2 for batches 2(l&3),+1.
// After MMA+gx: shfl_xor(16) exchanges -> every lane has i,f,g,o; act in registers; 1 bf16 store/lane.
static const int BS_PITCH_B = 528;                    // bytes per B-tile row (8 rows)
static const int SM_MBAR    = 8 * BS_PITCH_B;         // 4224
static const int LSTM_SMEM  = SM_MBAR + 128;

__global__ __launch_bounds__(256, 1) __cluster_dims__(CS, 1, 1)
void k_lstm(const float* __restrict__ Whf, const float* __restrict__ Whb)
{
    extern __shared__ __align__(1024) char sm[];
    uint32_t smb = smem_u32(sm);
    int d  = blockIdx.x >> 6;             // direction
    int be = (blockIdx.x >> 3) & 7;       // batch eighth
    uint32_t p;
    asm("mov.u32 %0, %%cluster_ctarank;" : "=r"(p));
    int hb = (int)p * 32;
    int tid = threadIdx.x;
    int w = tid >> 5, l = tid & 31;
    const float* W = d ? Whb : Whf;

    if (tid == 0) {
        asm volatile("mbarrier.init.shared.b64 [%0], %1;" :: "r"(smb + SM_MBAR),     "r"((uint32_t)CS) : "memory");
        asm volatile("mbarrier.init.shared.b64 [%0], %1;" :: "r"(smb + SM_MBAR + 8), "r"((uint32_t)CS) : "memory");
    }
    __syncthreads();
    asm volatile("barrier.cluster.arrive.aligned;" ::: "memory");
    asm volatile("barrier.cluster.wait.aligned;" ::: "memory");

    // ---- per-lane gate/hid mapping ----
    int g0    = l >> 4;                   // 0: gates {i,g}; 1: gates {f,o}
    int hid_l = (l >> 2) & 3;
    int cbl   = (l & 3) * 2;              // local batch col base
    int hw    = hb + 4*w + hid_l;         // global hid

    // ---- A fragments: rows r0 = gate g0, hid hw; r1 = gate g0+2, hid hw ----
    const float* wr0 = W + ((size_t)g0*H_ + hw)*(size_t)H_;
    const float* wr1 = W + ((size_t)(g0+2)*H_ + hw)*(size_t)H_;
    uint32_t A0[16], A1[16], A2[16], A3[16];
    {
        int kc0 = (l & 3)*2;
        #pragma unroll
        for (int kt = 0; kt < 16; kt++) {
            int kc = kt*16 + kc0;
            A0[kt] = packbf(wr0[kc],   wr0[kc+1]);
            A1[kt] = packbf(wr1[kc],   wr1[kc+1]);
            A2[kt] = packbf(wr0[kc+8], wr0[kc+9]);
            A3[kt] = packbf(wr1[kc+8], wr1[kc+9]);
        }
    }

    // ldsm lane row base (single n-tile of 8 local batches)
    uint32_t rowB = smb + (uint32_t)((l & 7)*BS_PITCH_B + (l >> 3)*16);

    // gx rows for this lane's two gate-rows
    int jg0 = g0*256 + hw;
    int jg1 = jg0 + 512;

    float c0 = 0.f, c1 = 0.f;
    const unsigned FULL = 0xffffffffu;

    uint32_t rem0 = 0, rem1 = 0;
    if (tid < CS) {
        rem0 = mapa_rank(smb + SM_MBAR,     (uint32_t)tid);
        rem1 = mapa_rank(smb + SM_MBAR + 8, (uint32_t)tid);
    }

    for (int s = 0; s < L_; s++) {
        int t = d ? (L_-1-s) : s;

        // ---- gx prefetch (independent of h) ----
        float2 gx0, gx1;
        {
            const float* base = g_gx + ((size_t)(d*L_ + t)*1024)*64 + 8*be + cbl;
            gx0 = *(const float2*)(base + (size_t)jg0*64);
            gx1 = *(const float2*)(base + (size_t)jg1*64);
        }

        // ---- wait + stage h (bf16 copy, this batch eighth: 4 KB) ----
        if (s == 0) {
            for (int i = tid; i < SM_MBAR/4; i += 256) ((uint32_t*)sm)[i] = 0;
        } else {
            int sp = s - 1;
            mbar_wait_cluster(smb + SM_MBAR + (sp & 1)*8, (uint32_t)((sp >> 1) & 1));
            int tprev = d ? (t+1) : (t-1);
            const uint4* hsrc = (const uint4*)(g_hb + (((size_t)d*L_ + tprev)*B_ + 8*be)*H_);
            int b = tid >> 5, kq = tid & 31;   // 256 uint4, one per thread
            *(uint4*)(sm + b*BS_PITCH_B + kq*16) = hsrc[tid];
        }
        __syncthreads();                       // sync A (stage visible; also orders prev-step ldsm before overwrite)

        // ---- MMA mainloop: D[16,8] per warp over K=256 ----
        float a0 = 0.f, a1 = 0.f, a2 = 0.f, a3 = 0.f;
        #pragma unroll
        for (int ktp = 0; ktp < 8; ktp++) {
            uint32_t b0, b1, b2, b3;
            ldsm_x4(b0, b1, b2, b3, rowB + ktp*64);
            mma16816(a0, a1, a2, a3, A0[2*ktp],   A1[2*ktp],   A2[2*ktp],   A3[2*ktp],   b0, b1);
            mma16816(a0, a1, a2, a3, A0[2*ktp+1], A1[2*ktp+1], A2[2*ktp+1], A3[2*ktp+1], b2, b3);
        }

        // ---- warp-local gate exchange + activations ----
        float u0 = a0 + gx0.x, u1 = a1 + gx0.y;     // gate g0,   batches cbl, cbl+1
        float u2 = a2 + gx1.x, u3 = a3 + gx1.y;     // gate g0+2, batches cbl, cbl+1
        float v0 = __shfl_xor_sync(FULL, u0, 16);
        float v1 = __shfl_xor_sync(FULL, u1, 16);
        float v2 = __shfl_xor_sync(FULL, u2, 16);
        float v3 = __shfl_xor_sync(FULL, u3, 16);
        // g0==0: u = {i, g}, v = {f, o};  g0==1: u = {f, o}, v = {i, g}
        float i0 = g0 ? v0 : u0,  f0 = g0 ? u0 : v0;
        float gI0 = g0 ? v2 : u2, o0 = g0 ? u2 : v2;
        float i1 = g0 ? v1 : u1,  f1 = g0 ? u1 : v1;
        float gI1 = g0 ? v3 : u3, o1 = g0 ? u3 : v3;

        c0 = sigap(f0)*c0 + sigap(i0)*tanhap(gI0);
        float h0 = sigap(o0)*tanhap(c0);
        c1 = sigap(f1)*c1 + sigap(i1)*tanhap(gI1);
        float h1 = sigap(o1)*tanhap(c1);

        // lane halves split the two batches for the store
        int bsel = cbl + g0;
        float hsel = g0 ? h1 : h0;
        g_hb[((size_t)(d*L_ + t)*B_ + 8*be + bsel)*H_ + hw] = __float2bfloat16(hsel);
        __syncthreads();                       // sync C (h stores done before release)
        if (tid < CS && s < L_-1) {
            mbar_arrive_remote((s & 1) ? rem1 : rem0);
        }
    }
}

// ---------------- emission GEMM: bf16 Hcat (R16-identical) ----------------
static const int EM_ROW4 = 66;
static const int EM_HC_BYTES = 64 * EM_ROW4 * 16;
static const int EMIT_SMEM = EM_HC_BYTES + 12*516*4;

__global__ __launch_bounds__(768, 2) void k_emit(const float* __restrict__ Wem,
                                                 const float* __restrict__ bem)
{
    extern __shared__ __align__(16) char smc[];
    uint4* Hc4 = (uint4*)smc;
    float* Wsm = (float*)(smc + EM_HC_BYTES);
    int l   = blockIdx.x;
    int tid = threadIdx.x;
    const uint4* hf  = (const uint4*)(g_hb + ((size_t)0*L_ + l)*B_*H_);
    const uint4* hbk = (const uint4*)(g_hb + ((size_t)1*L_ + l)*B_*H_);
    for (int e = tid; e < 2048; e += 768) {
        int r = e >> 5, kq = e & 31;
        Hc4[r*EM_ROW4 + kq]      = hf[e];
        Hc4[r*EM_ROW4 + 32 + kq] = hbk[e];
    }
    for (int e = tid; e < 12*512; e += 768)
        Wsm[(e >> 9)*516 + (e & 511)] = Wem[e];
    __syncthreads();

    int b = tid / 12, tg = tid - b*12;
    float acc = bem[tg];
    const uint2* hrow = (const uint2*)(Hc4 + b*EM_ROW4);
    const float4* wrow = (const float4*)(Wsm + tg*516);
    #pragma unroll 8
    for (int k4 = 0; k4 < 128; k4++) {
        uint2 hv = hrow[k4];
        float2 f01 = __bfloat1622float2(*(const __nv_bfloat162*)&hv.x);
        float2 f23 = __bfloat1622float2(*(const __nv_bfloat162*)&hv.y);
        float4 wv = wrow[k4];
        acc += wv.x*f01.x + wv.y*f01.y + wv.z*f23.x + wv.w*f23.y;
    }
    g_emit[((size_t)l*B_ + b)*T_ + tg] = acc;
}

// ---------------- CRF NLL: 2 batches per warp (ILP-2), fused mean ----------------
static const int CRF_SMEM = 2*512*12*4 + T_*T_*4 + 64;   // 49152 + 576 + 64

__global__ void k_crf(const int* __restrict__ tags, const float* __restrict__ trans,
                      float* __restrict__ out)
{
    extern __shared__ __align__(16) float scrf[];
    float* seA = scrf;                 // [512*12]
    float* seB = scrf + 512*12;        // [512*12]
    float* tr  = scrf + 2*512*12;      // [144]
    int b0 = 2*blockIdx.x, b1 = b0 + 1;
    int lane = threadIdx.x;
    for (int i = lane; i < T_*T_; i += 32) tr[i] = trans[i];
    {
        const float4* src = (const float4*)g_emit;
        float4* dA = (float4*)seA;
        float4* dB = (float4*)seB;
        for (int i = lane; i < 1536; i += 32) {
            int l = i / 3, j = i - 3*l;
            dA[i] = src[((size_t)l*64 + b0)*3 + j];
            dB[i] = src[((size_t)l*64 + b1)*3 + j];
        }
    }
    __syncwarp();

    const unsigned FULL = 0xffffffffu;
    const float I2 = 1.4426950408889634f;
    const float LN2 = 0.6931471805599453f;
    int mylane = (lane < T_) ? lane : 0;
    float trr2[T_];
    #pragma unroll
    for (int t2 = 0; t2 < T_; t2++) trr2[t2] = tr[t2*T_ + mylane] * I2;

    float aA = seA[mylane] * I2;
    float aB = seB[mylane] * I2;
    #pragma unroll 2
    for (int l = 1; l < L_; l++) {
        float eA = seA[l*12 + mylane] * I2;
        float eB = seB[l*12 + mylane] * I2;
        float vA[T_], vB[T_];
        #pragma unroll
        for (int t2 = 0; t2 < T_; t2++) {
            vA[t2] = __shfl_sync(FULL, aA, t2) + trr2[t2];
            vB[t2] = __shfl_sync(FULL, aB, t2) + trr2[t2];
        }
        float exA[T_], exB[T_];
        exA[0] = 1.0f; exB[0] = 1.0f;
        #pragma unroll
        for (int t2 = 1; t2 < T_; t2++) {
            exA[t2] = ex2f(vA[t2] - vA[0]);
            exB[t2] = ex2f(vB[t2] - vB[0]);
        }
        float sA = ((exA[0]+exA[1]) + (exA[2]+exA[3])) + ((exA[4]+exA[5]) + (exA[6]+exA[7]));
        sA += (exA[8]+exA[9]) + (exA[10]+exA[11]);
        float sB = ((exB[0]+exB[1]) + (exB[2]+exB[3])) + ((exB[4]+exB[5]) + (exB[6]+exB[7]));
        sB += (exB[8]+exB[9]) + (exB[10]+exB[11]);
        aA = vA[0] + lg2f(sA) + eA;
        aB = vB[0] + lg2f(sB) + eB;
    }
    float amA = (lane < T_) ? aA : -1e30f;
    float amB = (lane < T_) ? aB : -1e30f;
    float mmA = amA, mmB = amB;
    for (int o = 16; o; o >>= 1) {
        mmA = fmaxf(mmA, __shfl_xor_sync(FULL, mmA, o));
        mmB = fmaxf(mmB, __shfl_xor_sync(FULL, mmB, o));
    }
    float esA = (lane < T_) ? ex2f(aA - mmA) : 0.f;
    float esB = (lane < T_) ? ex2f(aB - mmB) : 0.f;
    for (int o = 16; o; o >>= 1) {
        esA += __shfl_xor_sync(FULL, esA, o);
        esB += __shfl_xor_sync(FULL, esB, o);
    }
    float logZA = (mmA + lg2f(esA)) * LN2;
    float logZB = (mmB + lg2f(esB)) * LN2;

    float egA = 0.f, tgA = 0.f, egB = 0.f, tgB = 0.f;
    for (int l = lane; l < L_; l += 32) {
        egA += seA[l*12 + tags[b0*L_ + l]];
        egB += seB[l*12 + tags[b1*L_ + l]];
    }
    for (int l = lane; l < L_-1; l += 32) {
        tgA += tr[tags[b0*L_ + l]*T_ + tags[b0*L_ + l + 1]];
        tgB += tr[tags[b1*L_ + l]*T_ + tags[b1*L_ + l + 1]];
    }
    for (int o = 16; o; o >>= 1) {
        egA += __shfl_xor_sync(FULL, egA, o);
        tgA += __shfl_xor_sync(FULL, tgA, o);
        egB += __shfl_xor_sync(FULL, egB, o);
        tgB += __shfl_xor_sync(FULL, tgB, o);
    }
    if (lane == 0) {
        g_nll[b0] = logZA - egA - tgA;
        g_nll[b1] = logZB - egB - tgB;
    }

    // fused mean: last finishing CTA reduces all 64 NLLs
    __shared__ int s_rank;
    if (lane == 0) {
        __threadfence();
        s_rank = atomicAdd(&g_done, 1);
    }
    __syncwarp();
    if (__shfl_sync(FULL, s_rank, 0) == 32 - 1) {
        __threadfence();
        float s = g_nll[lane] + g_nll[lane + 32];
        for (int o = 16; o; o >>= 1) s += __shfl_xor_sync(FULL, s, o);
        if (lane == 0) {
            out[0] = s / (float)B_;
            g_done = 0;
        }
    }
}

// ---------------- launch ----------------
extern "C" void kernel_launch(void* const* d_in, const int* in_sizes, int n_in,
                              void* d_out, int out_size)
{
    const int*   sent  = (const int*)  d_in[0];
    const int*   tags  = (const int*)  d_in[1];
    const float* emb   = (const float*)d_in[2];
    const float* Wihf  = (const float*)d_in[3];
    const float* Whhf  = (const float*)d_in[4];
    const float* bf    = (const float*)d_in[5];
    const float* Wihb  = (const float*)d_in[6];
    const float* Whhb  = (const float*)d_in[7];
    const float* bb    = (const float*)d_in[8];
    const float* Wem   = (const float*)d_in[9];
    const float* bem   = (const float*)d_in[10];
    const float* trans = (const float*)d_in[11];
    float* out = (float*)d_out;

    cudaFuncSetAttribute(k_ingate, cudaFuncAttributeMaxDynamicSharedMemorySize, INGATE_SMEM);
    cudaFuncSetAttribute(k_lstm,   cudaFuncAttributeMaxDynamicSharedMemorySize, LSTM_SMEM);
    cudaFuncSetAttribute(k_emit,   cudaFuncAttributeMaxDynamicSharedMemorySize, EMIT_SMEM);
    cudaFuncSetAttribute(k_crf,    cudaFuncAttributeMaxDynamicSharedMemorySize, CRF_SMEM);

    dim3 gA(32, 8);
    k_ingate<<<gA, 256, INGATE_SMEM>>>(sent, emb, Wihf, bf, Wihb, bb);
    k_lstm<<<128, 256, LSTM_SMEM>>>(Whhf, Whhb);
    k_emit<<<L_, 768, EMIT_SMEM>>>(Wem, bem);
    k_crf<<<32, 32, CRF_SMEM>>>(tags, trans, out);
}